// round 4
// baseline (speedup 1.0000x reference)
#include <cuda_runtime.h>

// Problem constants (fixed by the reference)
static constexpr int NENT = 50000;
static constexpr int CC   = 128;      // channels
static constexpr int C4   = 32;       // float4 per row
static constexpr int NRELM1 = 10;     // N_REL - 1

// Scratch (no cudaMalloc allowed). 16B-aligned for float4 / red.v4 access.
__device__ __align__(16) float g_emb[(size_t)NENT * CC];
__device__ __align__(16) float g_agg[(size_t)NENT * CC];
__device__ float g_cnt[NENT];

// ---------------------------------------------------------------------------
// Zero agg + cnt (run once at start; agg is re-zeroed by k_norm each hop)
// ---------------------------------------------------------------------------
__global__ void k_init() {
    const int stride = gridDim.x * blockDim.x;
    int i = blockIdx.x * blockDim.x + threadIdx.x;
    float4* agg4 = reinterpret_cast<float4*>(g_agg);
    const float4 z = make_float4(0.f, 0.f, 0.f, 0.f);
    for (int j = i; j < NENT * C4; j += stride) agg4[j] = z;
    for (int j = i; j < NENT;      j += stride) g_cnt[j] = 0.f;
}

// ---------------------------------------------------------------------------
// In-degree counts per head
// ---------------------------------------------------------------------------
__global__ void k_count(const int* __restrict__ head, int E) {
    int i = blockIdx.x * blockDim.x + threadIdx.x;
    if (i < E) atomicAdd(&g_cnt[head[i]], 1.0f);
}

// ---------------------------------------------------------------------------
// Edge kernel: warp per edge.
//   msg = emb[tail] * weight[type-1]   (float4 per lane)
//   red.global.add.v4.f32 into agg[head]
// ---------------------------------------------------------------------------
__global__ void k_edge(const float4* __restrict__ ext_emb, int use_ext,
                       const int* __restrict__ head,
                       const int* __restrict__ tail,
                       const int* __restrict__ etype,
                       const float4* __restrict__ w4,
                       int E) {
    __shared__ float4 sw[NRELM1 * C4];   // 5 KB relation table
    for (int i = threadIdx.x; i < NRELM1 * C4; i += blockDim.x) sw[i] = w4[i];
    __syncthreads();

    const int warp = (blockIdx.x * blockDim.x + threadIdx.x) >> 5;
    const int lane = threadIdx.x & 31;
    if (warp >= E) return;

    const int h  = head[warp];
    const int t  = tail[warp];
    const int ty = etype[warp] - 1;

    const float4* emb4 = use_ext ? ext_emb
                                 : reinterpret_cast<const float4*>(g_emb);

    float4 e = emb4[(long)t * C4 + lane];
    float4 r = sw[ty * C4 + lane];
    float4 m = make_float4(e.x * r.x, e.y * r.y, e.z * r.z, e.w * r.w);

    float* dst = &g_agg[(((long)h * C4) + lane) * 4];
    asm volatile("red.global.add.v4.f32 [%0], {%1,%2,%3,%4};"
                 :: "l"(dst), "f"(m.x), "f"(m.y), "f"(m.z), "f"(m.w)
                 : "memory");
}

// ---------------------------------------------------------------------------
// Normalize: warp per entity row.
//   agg /= max(cnt,1); L2-normalize (eps 1e-12); emb = n; out += n;
//   resets agg to 0 for the next hop (fused memset).
// ---------------------------------------------------------------------------
__global__ void k_norm(float4* __restrict__ out4) {
    const int warp = (blockIdx.x * blockDim.x + threadIdx.x) >> 5;
    const int lane = threadIdx.x & 31;
    if (warp >= NENT) return;

    float4* agg4 = reinterpret_cast<float4*>(g_agg);
    float4* emb4 = reinterpret_cast<float4*>(g_emb);
    const long idx = (long)warp * C4 + lane;

    float4 a = agg4[idx];
    agg4[idx] = make_float4(0.f, 0.f, 0.f, 0.f);   // ready for next hop

    const float invd = 1.0f / fmaxf(g_cnt[warp], 1.0f);
    a.x *= invd; a.y *= invd; a.z *= invd; a.w *= invd;

    float ss = a.x * a.x + a.y * a.y + a.z * a.z + a.w * a.w;
    #pragma unroll
    for (int o = 16; o > 0; o >>= 1)
        ss += __shfl_xor_sync(0xffffffffu, ss, o);

    const float inv = 1.0f / fmaxf(sqrtf(ss), 1e-12f);
    float4 n = make_float4(a.x * inv, a.y * inv, a.z * inv, a.w * inv);

    emb4[idx] = n;
    float4 o4 = out4[idx];
    out4[idx] = make_float4(o4.x + n.x, o4.y + n.y, o4.z + n.z, o4.w + n.w);
}

// ---------------------------------------------------------------------------
// Launch
// ---------------------------------------------------------------------------
extern "C" void kernel_launch(void* const* d_in, const int* in_sizes, int n_in,
                              void* d_out, int out_size) {
    const float* entity = (const float*)d_in[0];   // [NENT, C] f32
    const int*   eidx   = (const int*)d_in[1];     // [2, E] int32 (JAX x64 off)
    const int*   etype  = (const int*)d_in[2];     // [E]    int32
    const float* weight = (const float*)d_in[3];   // [10, C] f32
    float*       out    = (float*)d_out;

    const int E = in_sizes[2];
    const int* head = eidx;
    const int* tail = eidx + E;

    // res = entity_emb
    cudaMemcpyAsync(out, entity, (size_t)NENT * CC * sizeof(float),
                    cudaMemcpyDeviceToDevice, 0);

    k_init<<<1184, 256>>>();
    k_count<<<(E + 255) / 256, 256>>>(head, E);

    const float4* w4 = (const float4*)weight;
    const int eblocks = (E + 7) / 8;                // warp per edge, 8 warps/block
    const int nblocks = (NENT + 7) / 8;             // warp per entity

    for (int hop = 0; hop < 3; hop++) {
        k_edge<<<eblocks, 256>>>((const float4*)entity, hop == 0 ? 1 : 0,
                                 head, tail, etype, w4, E);
        k_norm<<<nblocks, 256>>>((float4*)out);
    }
}